// round 13
// baseline (speedup 1.0000x reference)
#include <cuda_runtime.h>
#include <cuda_bf16.h>
#include <math.h>
#include <stdint.h>

// Problem constants
#define CB 2
#define CT 2048
#define CD 2048
#define CN 16
#define CK 8
#define CH 128
#define CWIN 1024
#define CBT (CB*CT)

#define ROPE_QC (CB*CT*CN*64)
#define ROPE_KC (CB*CT*CK*64)

// Scratch (device globals; the exact 100.7MB set proven to pass the guard)
__device__ float g_q  [CBT*CN*CH];   // [B,T,N,H]
__device__ float g_k  [CBT*CK*CH];
__device__ float g_v  [CBT*CK*CH];
__device__ float g_enc[CBT*CN*CH];
__device__ float g_ts [64];

// ---------------------------------------------------------------------------
__global__ void rope_init_kernel() {
    int i = threadIdx.x;
    if (i < 64) g_ts[i] = (float)pow(10000.0, (double)i / 64.0);
}

__device__ __forceinline__ uint32_t pack_bf2(float x, float y) {
    __nv_bfloat162 h = __floats2bfloat162_rn(x, y);
    return *(uint32_t*)&h;
}

#define LDSM4(r, addr) \
    asm volatile("ldmatrix.sync.aligned.m8n8.x4.shared.b16 {%0,%1,%2,%3}, [%4];\n" \
        : "=r"((r)[0]), "=r"((r)[1]), "=r"((r)[2]), "=r"((r)[3]) : "r"(addr))
#define LDSM2T(r, addr) \
    asm volatile("ldmatrix.sync.aligned.m8n8.x2.trans.shared.b16 {%0,%1}, [%2];\n" \
        : "=r"((r)[0]), "=r"((r)[1]) : "r"(addr))
#define LDSM4T(r, addr) \
    asm volatile("ldmatrix.sync.aligned.m8n8.x4.trans.shared.b16 {%0,%1,%2,%3}, [%4];\n" \
        : "=r"((r)[0]), "=r"((r)[1]), "=r"((r)[2]), "=r"((r)[3]) : "r"(addr))
#define MMA16816(d, a, b) \
    asm volatile("mma.sync.aligned.m16n8k16.row.col.f32.bf16.bf16.f32 " \
        "{%0,%1,%2,%3}, {%4,%5,%6,%7}, {%8,%9}, {%0,%1,%2,%3};\n" \
        : "+f"((d)[0]), "+f"((d)[1]), "+f"((d)[2]), "+f"((d)[3]) \
        : "r"((a)[0]), "r"((a)[1]), "r"((a)[2]), "r"((a)[3]), "r"((b)[0]), "r"((b)[1]))

// ---------------------------------------------------------------------------
// Split-bf16 tensor-core GEMM (EXACT R4 structure; 2 CTAs/SM via launch bounds)
// ---------------------------------------------------------------------------
#define A_STR 40
#define B_STR 136
#define A_TILE (128*A_STR)
#define B_TILE (32*B_STR)
#define GEM_SMEM ((4*A_TILE + 4*B_TILE) * 2)

__device__ __forceinline__ void gemm_split_128x128(
    const float* __restrict__ A, int lda,
    const float* __restrict__ B, int ldb,
    float* __restrict__ C, int ldc, int Kd)
{
    extern __shared__ __nv_bfloat16 smg[];
    __nv_bfloat16* const sA = smg;
    __nv_bfloat16* const sB = smg + 4 * A_TILE;
    const uint32_t sAb = (uint32_t)__cvta_generic_to_shared(sA);
    const uint32_t sBb = (uint32_t)__cvta_generic_to_shared(sB);

    const int tid  = threadIdx.x;
    const int lane = tid & 31;
    const int wid  = tid >> 5;
    const int wm   = wid >> 2;
    const int wn   = wid & 3;

    const int ar = tid >> 1, ac = (tid & 1) * 4;
    const int br = tid >> 3, bc = (tid & 7) * 4;

    const float* Ap = A + (size_t)ar * lda + ac;
    const float* Bp = B + (size_t)br * ldb + bc;

    float acc[4][4][4];
#pragma unroll
    for (int a = 0; a < 4; ++a)
#pragma unroll
        for (int b = 0; b < 4; ++b)
#pragma unroll
            for (int c = 0; c < 4; ++c) acc[a][b][c] = 0.f;

    float4 av[4], bv[4];
#pragma unroll
    for (int q = 0; q < 4; ++q) {
        av[q] = *(const float4*)(Ap + q * 8);
        bv[q] = *(const float4*)(Bp + q * 32);
    }

    const int nIter = Kd >> 5;
    for (int it = 0; it < nIter; ++it) {
        const int cur = it & 1;
        __nv_bfloat16* aHi = sA + (2 * cur)     * A_TILE;
        __nv_bfloat16* aLo = sA + (2 * cur + 1) * A_TILE;
        __nv_bfloat16* bHi = sB + (2 * cur)     * B_TILE;
        __nv_bfloat16* bLo = sB + (2 * cur + 1) * B_TILE;

#pragma unroll
        for (int q = 0; q < 4; ++q) {
            float a0 = av[q].x, a1 = av[q].y, a2 = av[q].z, a3 = av[q].w;
            float h0 = __bfloat162float(__float2bfloat16(a0));
            float h1 = __bfloat162float(__float2bfloat16(a1));
            float h2 = __bfloat162float(__float2bfloat16(a2));
            float h3 = __bfloat162float(__float2bfloat16(a3));
            uint2 H = make_uint2(pack_bf2(h0, h1), pack_bf2(h2, h3));
            uint2 L = make_uint2(pack_bf2(a0 - h0, a1 - h1), pack_bf2(a2 - h2, a3 - h3));
            *(uint2*)(aHi + ar * A_STR + ac + q * 8) = H;
            *(uint2*)(aLo + ar * A_STR + ac + q * 8) = L;

            float b0 = bv[q].x, b1 = bv[q].y, b2 = bv[q].z, b3 = bv[q].w;
            float g0 = __bfloat162float(__float2bfloat16(b0));
            float g1 = __bfloat162float(__float2bfloat16(b1));
            float g2 = __bfloat162float(__float2bfloat16(b2));
            float g3 = __bfloat162float(__float2bfloat16(b3));
            H = make_uint2(pack_bf2(g0, g1), pack_bf2(g2, g3));
            L = make_uint2(pack_bf2(b0 - g0, b1 - g1), pack_bf2(b2 - g2, b3 - g3));
            *(uint2*)(bHi + br * B_STR + bc + q * 32) = H;
            *(uint2*)(bLo + br * B_STR + bc + q * 32) = L;
        }
        __syncthreads();

        if (it + 1 < nIter) {
            const float* An = Ap + (it + 1) * 32;
            const float* Bn = Bp + (size_t)(it + 1) * 32 * ldb;
#pragma unroll
            for (int q = 0; q < 4; ++q) {
                av[q] = *(const float4*)(An + q * 8);
                bv[q] = *(const float4*)(Bn + q * 32);
            }
        }

        const uint32_t aHiB = sAb + (2 * cur)     * A_TILE * 2;
        const uint32_t aLoB = sAb + (2 * cur + 1) * A_TILE * 2;
        const uint32_t bHiB = sBb + (2 * cur)     * B_TILE * 2;
        const uint32_t bLoB = sBb + (2 * cur + 1) * B_TILE * 2;

#pragma unroll
        for (int ks = 0; ks < 32; ks += 16) {
            uint32_t bhi[4][2], blo[4][2];
#pragma unroll
            for (int nt = 0; nt < 4; ++nt) {
                uint32_t off = (ks + (lane & 15)) * (B_STR * 2) + (wn * 32 + nt * 8) * 2;
                LDSM2T(bhi[nt], bHiB + off);
                LDSM2T(blo[nt], bLoB + off);
            }
#pragma unroll
            for (int mt = 0; mt < 4; ++mt) {
                int row = wm * 64 + mt * 16 + (lane & 15);
                uint32_t off = row * (A_STR * 2) + ks * 2 + (lane >> 4) * 16;
                uint32_t ahi[4], alo[4];
                LDSM4(ahi, aHiB + off);
                LDSM4(alo, aLoB + off);
#pragma unroll
                for (int nt = 0; nt < 4; ++nt) {
                    MMA16816(acc[mt][nt], ahi, bhi[nt]);
                    MMA16816(acc[mt][nt], alo, bhi[nt]);
                    MMA16816(acc[mt][nt], ahi, blo[nt]);
                }
            }
        }
    }

    const int rg = lane >> 2, tg = lane & 3;
#pragma unroll
    for (int mt = 0; mt < 4; ++mt)
#pragma unroll
        for (int nt = 0; nt < 4; ++nt) {
            int r = wm * 64 + mt * 16 + rg;
            int c = wn * 32 + nt * 8 + tg * 2;
            *(float2*)&C[(size_t)r * ldc + c]       = make_float2(acc[mt][nt][0], acc[mt][nt][1]);
            *(float2*)&C[(size_t)(r + 8) * ldc + c] = make_float2(acc[mt][nt][2], acc[mt][nt][3]);
        }
}

// ---------------------------------------------------------------------------
__global__ __launch_bounds__(256, 2) void qkv_kernel(
    const float* __restrict__ x,
    const float* __restrict__ wq,
    const float* __restrict__ wkv)
{
    const int m0 = blockIdx.x * 128;
    const int h  = blockIdx.y;
    const float* A = x + (size_t)m0 * CD;
    const float* W;
    float* C; int ldc;
    if (h < CN) {
        W = wq + (size_t)h * CD * CH;
        C = g_q + (size_t)m0 * CN * CH + h * CH; ldc = CN * CH;
    } else if (h < CN + CK) {
        const int kk = h - CN;
        W = wkv + (size_t)kk * CD * CH;
        C = g_k + (size_t)m0 * CK * CH + kk * CH; ldc = CK * CH;
    } else {
        const int kk = h - CN - CK;
        W = wkv + (size_t)(CK + kk) * CD * CH;
        C = g_v + (size_t)m0 * CK * CH + kk * CH; ldc = CK * CH;
    }
    gemm_split_128x128(A, CD, W, CH, C, ldc, CD);
}

__global__ __launch_bounds__(256, 2) void oproj_kernel(
    const float* __restrict__ wo, float* __restrict__ out)
{
    const int m0 = blockIdx.x * 128;
    const int n0 = blockIdx.y * 128;
    gemm_split_128x128(g_enc + (size_t)m0 * (CN*CH), CN*CH,
                       wo + n0, CD,
                       out + (size_t)m0 * CD + n0, CD, CN*CH);
}

// ---------------------------------------------------------------------------
__global__ __launch_bounds__(256) void rope_kernel(const int* __restrict__ seg)
{
    int idx = blockIdx.x * blockDim.x + threadIdx.x;
    if (idx >= ROPE_QC + ROPE_KC) return;

    float* buf; int heads; float scal; int lidx;
    if (idx < ROPE_QC) {
        buf = g_q; heads = CN; scal = 0.08838834764831845f; lidx = idx;
    } else {
        buf = g_k; heads = CK; scal = 1.0f; lidx = idx - ROPE_QC;
    }
    const int i    = lidx & 63;
    const int rest = lidx >> 6;
    const int bt   = rest / heads;
    const int pos  = seg[bt];

    float ts = g_ts[i];
    float ang = (float)pos / ts;
    float s, c;
    sincosf(ang, &s, &c);

    float* p = buf + (size_t)rest * CH;
    float x1 = p[i];
    float x2 = p[i + 64];
    p[i]      = (x1 * c - x2 * s) * scal;
    p[i + 64] = (x2 * c + x1 * s) * scal;
}

// ---------------------------------------------------------------------------
__device__ __forceinline__ float softcap(float v)
{
    float x = v * (1.0f / 50.0f);
    float ax = fabsf(x);
    if (ax < 0.25f) {
        float x2 = x * x;
        float t = x * (1.0f + x2 * (-1.0f/3.0f + x2 * (2.0f/15.0f + x2 * (-17.0f/315.0f))));
        return t * 50.0f;
    }
    return tanhf(x) * 50.0f;
}

// ---------------------------------------------------------------------------
// Tensor-core flash attention (R9 version; measured equal to R8)
// ---------------------------------------------------------------------------
#define AROW 272
#define QTILE (128*AROW)
#define KTILE (64*AROW)
#define ASTG  (4*KTILE)
#define AKV0  (2*QTILE)
#define ATT_SMEM (AKV0 + 2*ASTG)

__global__ __launch_bounds__(256, 1) void attn_kernel()
{
    extern __shared__ char sma[];
    const uint32_t sb = (uint32_t)__cvta_generic_to_shared(sma);

    const int tid = threadIdx.x, lane = tid & 31, w = tid >> 5;
    const int rg = lane >> 2, tg = lane & 3;
    const int qt = blockIdx.x, n = blockIdx.y, b = blockIdx.z;
    const int kk = n >> 1;
    const int q0 = qt * 128;
    const int row0 = w * 16;

#pragma unroll
    for (int p = 0; p < 16; ++p) {
        int idx = tid + p * 256;
        int r = idx >> 5, c4 = idx & 31;
        float4 f = *(const float4*)(g_q +
            ((size_t)(b*CT + q0 + r) * CN + n) * CH + c4 * 4);
        float h0 = __bfloat162float(__float2bfloat16(f.x));
        float h1 = __bfloat162float(__float2bfloat16(f.y));
        float h2 = __bfloat162float(__float2bfloat16(f.z));
        float h3 = __bfloat162float(__float2bfloat16(f.w));
        uint32_t off = (uint32_t)(r * AROW + c4 * 8);
        *(uint2*)(sma + off)         = make_uint2(pack_bf2(h0, h1), pack_bf2(h2, h3));
        *(uint2*)(sma + QTILE + off) = make_uint2(pack_bf2(f.x - h0, f.y - h1),
                                                  pack_bf2(f.z - h2, f.w - h3));
    }

    int st0 = q0 - (CWIN - 1); if (st0 < 0) st0 = 0; st0 >>= 6;
    const int stL = (q0 + 127) >> 6;

    float4 kreg[8], vreg[8];
    const int sr = tid >> 5, sc = tid & 31;

    auto ldKV = [&](int st) {
        const int s0 = st * 64;
#pragma unroll
        for (int p = 0; p < 8; ++p) {
            int r = sr + p * 8;
            size_t off = ((size_t)(b*CT + s0 + r) * CK + kk) * CH + sc * 4;
            kreg[p] = *(const float4*)(g_k + off);
            vreg[p] = *(const float4*)(g_v + off);
        }
    };
    auto stKV = [&](int bsel) {
        const uint32_t kb = AKV0 + bsel * ASTG;
#pragma unroll
        for (int p = 0; p < 8; ++p) {
            int r = sr + p * 8;
            uint32_t off = (uint32_t)(r * AROW + sc * 8);
            float4 f = kreg[p];
            float h0 = __bfloat162float(__float2bfloat16(f.x));
            float h1 = __bfloat162float(__float2bfloat16(f.y));
            float h2 = __bfloat162float(__float2bfloat16(f.z));
            float h3 = __bfloat162float(__float2bfloat16(f.w));
            *(uint2*)(sma + kb + off) = make_uint2(pack_bf2(h0, h1), pack_bf2(h2, h3));
            *(uint2*)(sma + kb + KTILE + off) =
                make_uint2(pack_bf2(f.x - h0, f.y - h1), pack_bf2(f.z - h2, f.w - h3));
            f = vreg[p];
            h0 = __bfloat162float(__float2bfloat16(f.x));
            h1 = __bfloat162float(__float2bfloat16(f.y));
            h2 = __bfloat162float(__float2bfloat16(f.z));
            h3 = __bfloat162float(__float2bfloat16(f.w));
            *(uint2*)(sma + kb + 2*KTILE + off) = make_uint2(pack_bf2(h0, h1), pack_bf2(h2, h3));
            *(uint2*)(sma + kb + 3*KTILE + off) =
                make_uint2(pack_bf2(f.x - h0, f.y - h1), pack_bf2(f.z - h2, f.w - h3));
        }
    };

    ldKV(st0);
    stKV(0);
    if (st0 + 1 <= stL) ldKV(st0 + 1);
    __syncthreads();

    float m_i[2] = {-1e30f, -1e30f}, l_i[2] = {0.f, 0.f};
    float ao[16][4];
#pragma unroll
    for (int t = 0; t < 16; ++t)
#pragma unroll
        for (int c = 0; c < 4; ++c) ao[t][c] = 0.f;

    for (int st = st0; st <= stL; ++st) {
        const int bsel = (st - st0) & 1;
        const uint32_t kb  = sb + AKV0 + bsel * ASTG;
        const uint32_t vhB = kb + 2*KTILE;
        const int s0 = st * 64;

        float as[8][4];
#pragma unroll
        for (int nt = 0; nt < 8; ++nt)
#pragma unroll
            for (int c = 0; c < 4; ++c) as[nt][c] = 0.f;

#pragma unroll
        for (int kc = 0; kc < 8; ++kc) {
            uint32_t qa = sb + (row0 + (lane & 15)) * AROW + kc*32 + (lane >> 4) * 16;
            uint32_t qh[4], ql[4];
            LDSM4(qh, qa);
            LDSM4(ql, qa + QTILE);
#pragma unroll
            for (int ntp = 0; ntp < 4; ++ntp) {
                uint32_t ka = kb + (ntp*16 + (lane >> 4)*8 + (lane & 7)) * AROW
                            + kc*32 + ((lane >> 3) & 1) * 16;
                uint32_t kh4[4], kl4[4];
                LDSM4(kh4, ka);
                LDSM4(kl4, ka + KTILE);
#pragma unroll
                for (int j = 0; j < 2; ++j) {
                    const int nt = ntp*2 + j;
                    MMA16816(as[nt], qh, &kh4[2*j]);
                    MMA16816(as[nt], ql, &kh4[2*j]);
                    MMA16816(as[nt], qh, &kl4[2*j]);
                }
            }
        }

        float scale_[2];
#pragma unroll
        for (int hf = 0; hf < 2; ++hf) {
            const int qrow = q0 + row0 + rg + hf*8;
            float rm = -1e30f;
#pragma unroll
            for (int nt = 0; nt < 8; ++nt)
#pragma unroll
                for (int cc = 0; cc < 2; ++cc) {
                    const int scol = s0 + nt*8 + tg*2 + cc;
                    float xx = softcap(as[nt][hf*2 + cc]);
                    const bool valid = (scol <= qrow) && (qrow - scol < CWIN);
                    xx = valid ? xx : -1e30f;
                    as[nt][hf*2 + cc] = xx;
                    rm = fmaxf(rm, xx);
                }
            rm = fmaxf(rm, __shfl_xor_sync(0xffffffffu, rm, 1));
            rm = fmaxf(rm, __shfl_xor_sync(0xffffffffu, rm, 2));

            const float mn = fmaxf(m_i[hf], rm);
            scale_[hf] = __expf(m_i[hf] - mn);
            m_i[hf] = mn;

            float sl = 0.f;
#pragma unroll
            for (int nt = 0; nt < 8; ++nt)
#pragma unroll
                for (int cc = 0; cc < 2; ++cc) {
                    float v = as[nt][hf*2 + cc];
                    float p = (v > -1e29f) ? __expf(v - mn) : 0.f;
                    as[nt][hf*2 + cc] = p;
                    sl += p;
                }
            sl += __shfl_xor_sync(0xffffffffu, sl, 1);
            sl += __shfl_xor_sync(0xffffffffu, sl, 2);
            l_i[hf] = l_i[hf] * scale_[hf] + sl;
        }
#pragma unroll
        for (int nt = 0; nt < 16; ++nt) {
            ao[nt][0] *= scale_[0]; ao[nt][1] *= scale_[0];
            ao[nt][2] *= scale_[1]; ao[nt][3] *= scale_[1];
        }

        if (st < stL) stKV(bsel ^ 1);
        if (st + 2 <= stL) ldKV(st + 2);

#pragma unroll
        for (int kc = 0; kc < 4; ++kc) {
            uint32_t ph[4], pl[4];
#pragma unroll
            for (int half = 0; half < 2; ++half) {
                const int nt = 2*kc + half;
                float p0 = as[nt][0], p1 = as[nt][1], p2 = as[nt][2], p3 = as[nt][3];
                float h0 = __bfloat162float(__float2bfloat16(p0));
                float h1 = __bfloat162float(__float2bfloat16(p1));
                float h2 = __bfloat162float(__float2bfloat16(p2));
                float h3 = __bfloat162float(__float2bfloat16(p3));
                ph[half*2 + 0] = pack_bf2(p0, p1);
                ph[half*2 + 1] = pack_bf2(p2, p3);
                pl[half*2 + 0] = pack_bf2(p0 - h0, p1 - h1);
                pl[half*2 + 1] = pack_bf2(p2 - h2, p3 - h3);
            }
#pragma unroll
            for (int ntp = 0; ntp < 8; ++ntp) {
                uint32_t va = vhB + (kc*16 + (lane & 15)) * AROW
                            + ntp*32 + (lane >> 4) * 16;
                uint32_t vh4[4], vl4[4];
                LDSM4T(vh4, va);
                LDSM4T(vl4, va + KTILE);
#pragma unroll
                for (int j = 0; j < 2; ++j) {
                    const int nt = ntp*2 + j;
                    MMA16816(ao[nt], ph, &vh4[2*j]);
                    MMA16816(ao[nt], pl, &vh4[2*j]);
                    MMA16816(ao[nt], ph, &vl4[2*j]);
                }
            }
        }

        __syncthreads();
    }

#pragma unroll
    for (int hf = 0; hf < 2; ++hf) {
        const int qrow = q0 + row0 + rg + hf*8;
        const float inv = 1.0f / l_i[hf];
        float* o = g_enc + ((size_t)(b*CT + qrow) * CN + n) * CH;
#pragma unroll
        for (int nt = 0; nt < 16; ++nt)
            *(float2*)(o + nt*8 + tg*2) =
                make_float2(ao[nt][hf*2 + 0] * inv, ao[nt][hf*2 + 1] * inv);
    }
}

// ---------------------------------------------------------------------------
extern "C" void kernel_launch(void* const* d_in, const int* in_sizes, int n_in,
                              void* d_out, int out_size)
{
    const float* x   = (const float*)d_in[0];
    const float* wq  = (const float*)d_in[1];
    const float* wkv = (const float*)d_in[2];
    const float* wo  = (const float*)d_in[3];
    const int*   seg = (const int*)d_in[4];
    float* out = (float*)d_out;

    cudaFuncSetAttribute(attn_kernel,
                         cudaFuncAttributeMaxDynamicSharedMemorySize, ATT_SMEM);
    cudaFuncSetAttribute(qkv_kernel,
                         cudaFuncAttributeMaxDynamicSharedMemorySize, GEM_SMEM);
    cudaFuncSetAttribute(oproj_kernel,
                         cudaFuncAttributeMaxDynamicSharedMemorySize, GEM_SMEM);

    rope_init_kernel<<<1, 64>>>();
    qkv_kernel<<<dim3(32, 32), 256, GEM_SMEM>>>(x, wq, wkv);
    rope_kernel<<<(ROPE_QC + ROPE_KC + 255)/256, 256>>>(seg);
    attn_kernel<<<dim3(CT/128, CN, CB), 256, ATT_SMEM>>>();
    oproj_kernel<<<dim3(32, 16), 256, GEM_SMEM>>>(wo, out);
}

// round 15
// speedup vs baseline: 1.0998x; 1.0998x over previous
#include <cuda_runtime.h>
#include <cuda_bf16.h>
#include <math.h>
#include <stdint.h>

// Problem constants
#define CB 2
#define CT 2048
#define CD 2048
#define CN 16
#define CK 8
#define CH 128
#define CWIN 1024
#define CBT (CB*CT)

#define ROPE_QC (CB*CT*CN*64)
#define ROPE_KC (CB*CT*CK*64)

// Scratch (device globals; the exact 100.7MB set proven to pass the guard)
__device__ float g_q  [CBT*CN*CH];   // [B,T,N,H]
__device__ float g_k  [CBT*CK*CH];
__device__ float g_v  [CBT*CK*CH];
__device__ float g_enc[CBT*CN*CH];
__device__ float g_ts [64];

// ---------------------------------------------------------------------------
__global__ void rope_init_kernel() {
    int i = threadIdx.x;
    if (i < 64) g_ts[i] = (float)pow(10000.0, (double)i / 64.0);
}

__device__ __forceinline__ uint32_t pack_bf2(float x, float y) {
    __nv_bfloat162 h = __floats2bfloat162_rn(x, y);
    return *(uint32_t*)&h;
}

#define LDSM4(r, addr) \
    asm volatile("ldmatrix.sync.aligned.m8n8.x4.shared.b16 {%0,%1,%2,%3}, [%4];\n" \
        : "=r"((r)[0]), "=r"((r)[1]), "=r"((r)[2]), "=r"((r)[3]) : "r"(addr))
#define LDSM2T(r, addr) \
    asm volatile("ldmatrix.sync.aligned.m8n8.x2.trans.shared.b16 {%0,%1}, [%2];\n" \
        : "=r"((r)[0]), "=r"((r)[1]) : "r"(addr))
#define LDSM4T(r, addr) \
    asm volatile("ldmatrix.sync.aligned.m8n8.x4.trans.shared.b16 {%0,%1,%2,%3}, [%4];\n" \
        : "=r"((r)[0]), "=r"((r)[1]), "=r"((r)[2]), "=r"((r)[3]) : "r"(addr))
#define MMA16816(d, a, b) \
    asm volatile("mma.sync.aligned.m16n8k16.row.col.f32.bf16.bf16.f32 " \
        "{%0,%1,%2,%3}, {%4,%5,%6,%7}, {%8,%9}, {%0,%1,%2,%3};\n" \
        : "+f"((d)[0]), "+f"((d)[1]), "+f"((d)[2]), "+f"((d)[3]) \
        : "r"((a)[0]), "r"((a)[1]), "r"((a)[2]), "r"((a)[3]), "r"((b)[0]), "r"((b)[1]))

// ---------------------------------------------------------------------------
// Split-bf16 tensor-core GEMM (EXACT R8 form — at mma.sync issue ceiling)
// ---------------------------------------------------------------------------
#define A_STR 40
#define B_STR 136
#define A_TILE (128*A_STR)
#define B_TILE (32*B_STR)
#define GEM_SMEM ((4*A_TILE + 4*B_TILE) * 2)

__device__ __forceinline__ void gemm_split_128x128(
    const float* __restrict__ A, int lda,
    const float* __restrict__ B, int ldb,
    float* __restrict__ C, int ldc, int Kd)
{
    extern __shared__ __nv_bfloat16 smg[];
    __nv_bfloat16* const sA = smg;
    __nv_bfloat16* const sB = smg + 4 * A_TILE;
    const uint32_t sAb = (uint32_t)__cvta_generic_to_shared(sA);
    const uint32_t sBb = (uint32_t)__cvta_generic_to_shared(sB);

    const int tid  = threadIdx.x;
    const int lane = tid & 31;
    const int wid  = tid >> 5;
    const int wm   = wid >> 2;
    const int wn   = wid & 3;

    const int ar = tid >> 1, ac = (tid & 1) * 4;
    const int br = tid >> 3, bc = (tid & 7) * 4;

    const float* Ap = A + (size_t)ar * lda + ac;
    const float* Bp = B + (size_t)br * ldb + bc;

    float acc[4][4][4];
#pragma unroll
    for (int a = 0; a < 4; ++a)
#pragma unroll
        for (int b = 0; b < 4; ++b)
#pragma unroll
            for (int c = 0; c < 4; ++c) acc[a][b][c] = 0.f;

    float4 av[4], bv[4];
#pragma unroll
    for (int q = 0; q < 4; ++q) {
        av[q] = *(const float4*)(Ap + q * 8);
        bv[q] = *(const float4*)(Bp + q * 32);
    }

    const int nIter = Kd >> 5;
    for (int it = 0; it < nIter; ++it) {
        const int cur = it & 1;
        __nv_bfloat16* aHi = sA + (2 * cur)     * A_TILE;
        __nv_bfloat16* aLo = sA + (2 * cur + 1) * A_TILE;
        __nv_bfloat16* bHi = sB + (2 * cur)     * B_TILE;
        __nv_bfloat16* bLo = sB + (2 * cur + 1) * B_TILE;

#pragma unroll
        for (int q = 0; q < 4; ++q) {
            float a0 = av[q].x, a1 = av[q].y, a2 = av[q].z, a3 = av[q].w;
            float h0 = __bfloat162float(__float2bfloat16(a0));
            float h1 = __bfloat162float(__float2bfloat16(a1));
            float h2 = __bfloat162float(__float2bfloat16(a2));
            float h3 = __bfloat162float(__float2bfloat16(a3));
            uint2 H = make_uint2(pack_bf2(h0, h1), pack_bf2(h2, h3));
            uint2 L = make_uint2(pack_bf2(a0 - h0, a1 - h1), pack_bf2(a2 - h2, a3 - h3));
            *(uint2*)(aHi + ar * A_STR + ac + q * 8) = H;
            *(uint2*)(aLo + ar * A_STR + ac + q * 8) = L;

            float b0 = bv[q].x, b1 = bv[q].y, b2 = bv[q].z, b3 = bv[q].w;
            float g0 = __bfloat162float(__float2bfloat16(b0));
            float g1 = __bfloat162float(__float2bfloat16(b1));
            float g2 = __bfloat162float(__float2bfloat16(b2));
            float g3 = __bfloat162float(__float2bfloat16(b3));
            H = make_uint2(pack_bf2(g0, g1), pack_bf2(g2, g3));
            L = make_uint2(pack_bf2(b0 - g0, b1 - g1), pack_bf2(b2 - g2, b3 - g3));
            *(uint2*)(bHi + br * B_STR + bc + q * 32) = H;
            *(uint2*)(bLo + br * B_STR + bc + q * 32) = L;
        }
        __syncthreads();

        if (it + 1 < nIter) {
            const float* An = Ap + (it + 1) * 32;
            const float* Bn = Bp + (size_t)(it + 1) * 32 * ldb;
#pragma unroll
            for (int q = 0; q < 4; ++q) {
                av[q] = *(const float4*)(An + q * 8);
                bv[q] = *(const float4*)(Bn + q * 32);
            }
        }

        const uint32_t aHiB = sAb + (2 * cur)     * A_TILE * 2;
        const uint32_t aLoB = sAb + (2 * cur + 1) * A_TILE * 2;
        const uint32_t bHiB = sBb + (2 * cur)     * B_TILE * 2;
        const uint32_t bLoB = sBb + (2 * cur + 1) * B_TILE * 2;

#pragma unroll
        for (int ks = 0; ks < 32; ks += 16) {
            uint32_t bhi[4][2], blo[4][2];
#pragma unroll
            for (int nt = 0; nt < 4; ++nt) {
                uint32_t off = (ks + (lane & 15)) * (B_STR * 2) + (wn * 32 + nt * 8) * 2;
                LDSM2T(bhi[nt], bHiB + off);
                LDSM2T(blo[nt], bLoB + off);
            }
#pragma unroll
            for (int mt = 0; mt < 4; ++mt) {
                int row = wm * 64 + mt * 16 + (lane & 15);
                uint32_t off = row * (A_STR * 2) + ks * 2 + (lane >> 4) * 16;
                uint32_t ahi[4], alo[4];
                LDSM4(ahi, aHiB + off);
                LDSM4(alo, aLoB + off);
#pragma unroll
                for (int nt = 0; nt < 4; ++nt) {
                    MMA16816(acc[mt][nt], ahi, bhi[nt]);
                    MMA16816(acc[mt][nt], alo, bhi[nt]);
                    MMA16816(acc[mt][nt], ahi, blo[nt]);
                }
            }
        }
    }

    const int rg = lane >> 2, tg = lane & 3;
#pragma unroll
    for (int mt = 0; mt < 4; ++mt)
#pragma unroll
        for (int nt = 0; nt < 4; ++nt) {
            int r = wm * 64 + mt * 16 + rg;
            int c = wn * 32 + nt * 8 + tg * 2;
            *(float2*)&C[(size_t)r * ldc + c]       = make_float2(acc[mt][nt][0], acc[mt][nt][1]);
            *(float2*)&C[(size_t)(r + 8) * ldc + c] = make_float2(acc[mt][nt][2], acc[mt][nt][3]);
        }
}

// ---------------------------------------------------------------------------
__global__ __launch_bounds__(256, 1) void qkv_kernel(
    const float* __restrict__ x,
    const float* __restrict__ wq,
    const float* __restrict__ wkv)
{
    const int m0 = blockIdx.x * 128;
    const int h  = blockIdx.y;
    const float* A = x + (size_t)m0 * CD;
    const float* W;
    float* C; int ldc;
    if (h < CN) {
        W = wq + (size_t)h * CD * CH;
        C = g_q + (size_t)m0 * CN * CH + h * CH; ldc = CN * CH;
    } else if (h < CN + CK) {
        const int kk = h - CN;
        W = wkv + (size_t)kk * CD * CH;
        C = g_k + (size_t)m0 * CK * CH + kk * CH; ldc = CK * CH;
    } else {
        const int kk = h - CN - CK;
        W = wkv + (size_t)(CK + kk) * CD * CH;
        C = g_v + (size_t)m0 * CK * CH + kk * CH; ldc = CK * CH;
    }
    gemm_split_128x128(A, CD, W, CH, C, ldc, CD);
}

__global__ __launch_bounds__(256, 1) void oproj_kernel(
    const float* __restrict__ wo, float* __restrict__ out)
{
    const int m0 = blockIdx.x * 128;
    const int n0 = blockIdx.y * 128;
    gemm_split_128x128(g_enc + (size_t)m0 * (CN*CH), CN*CH,
                       wo + n0, CD,
                       out + (size_t)m0 * CD + n0, CD, CN*CH);
}

// ---------------------------------------------------------------------------
__global__ __launch_bounds__(256) void rope_kernel(const int* __restrict__ seg)
{
    int idx = blockIdx.x * blockDim.x + threadIdx.x;
    if (idx >= ROPE_QC + ROPE_KC) return;

    float* buf; int heads; float scal; int lidx;
    if (idx < ROPE_QC) {
        buf = g_q; heads = CN; scal = 0.08838834764831845f; lidx = idx;
    } else {
        buf = g_k; heads = CK; scal = 1.0f; lidx = idx - ROPE_QC;
    }
    const int i    = lidx & 63;
    const int rest = lidx >> 6;
    const int bt   = rest / heads;
    const int pos  = seg[bt];

    float ts = g_ts[i];
    float ang = (float)pos / ts;
    float s, c;
    sincosf(ang, &s, &c);

    float* p = buf + (size_t)rest * CH;
    float x1 = p[i];
    float x2 = p[i + 64];
    p[i]      = (x1 * c - x2 * s) * scal;
    p[i + 64] = (x2 * c + x1 * s) * scal;
}

// ---------------------------------------------------------------------------
__device__ __forceinline__ float softcap(float v)
{
    float x = v * (1.0f / 50.0f);
    float ax = fabsf(x);
    if (ax < 0.25f) {
        float x2 = x * x;
        float t = x * (1.0f + x2 * (-1.0f/3.0f + x2 * (2.0f/15.0f + x2 * (-17.0f/315.0f))));
        return t * 50.0f;
    }
    return tanhf(x) * 50.0f;
}

// ---------------------------------------------------------------------------
// Tensor-core flash attention. stKV/ldKV hoisted to the TOP of each step so
// the split's ALU work interleaves under the QK mma block (tensor-busy) and
// next-step LDGs get a full step of latency cover.
// ---------------------------------------------------------------------------
#define AROW 272
#define QTILE (128*AROW)
#define KTILE (64*AROW)
#define ASTG  (4*KTILE)
#define AKV0  (2*QTILE)
#define ATT_SMEM (AKV0 + 2*ASTG)

__global__ __launch_bounds__(256, 1) void attn_kernel()
{
    extern __shared__ char sma[];
    const uint32_t sb = (uint32_t)__cvta_generic_to_shared(sma);

    const int tid = threadIdx.x, lane = tid & 31, w = tid >> 5;
    const int rg = lane >> 2, tg = lane & 3;
    const int qt = blockIdx.x, n = blockIdx.y, b = blockIdx.z;
    const int kk = n >> 1;
    const int q0 = qt * 128;
    const int row0 = w * 16;

#pragma unroll
    for (int p = 0; p < 16; ++p) {
        int idx = tid + p * 256;
        int r = idx >> 5, c4 = idx & 31;
        float4 f = *(const float4*)(g_q +
            ((size_t)(b*CT + q0 + r) * CN + n) * CH + c4 * 4);
        float h0 = __bfloat162float(__float2bfloat16(f.x));
        float h1 = __bfloat162float(__float2bfloat16(f.y));
        float h2 = __bfloat162float(__float2bfloat16(f.z));
        float h3 = __bfloat162float(__float2bfloat16(f.w));
        uint32_t off = (uint32_t)(r * AROW + c4 * 8);
        *(uint2*)(sma + off)         = make_uint2(pack_bf2(h0, h1), pack_bf2(h2, h3));
        *(uint2*)(sma + QTILE + off) = make_uint2(pack_bf2(f.x - h0, f.y - h1),
                                                  pack_bf2(f.z - h2, f.w - h3));
    }

    int st0 = q0 - (CWIN - 1); if (st0 < 0) st0 = 0; st0 >>= 6;
    const int stL = (q0 + 127) >> 6;

    float4 kreg[8], vreg[8];
    const int sr = tid >> 5, sc = tid & 31;

    auto ldKV = [&](int st) {
        const int s0 = st * 64;
#pragma unroll
        for (int p = 0; p < 8; ++p) {
            int r = sr + p * 8;
            size_t off = ((size_t)(b*CT + s0 + r) * CK + kk) * CH + sc * 4;
            kreg[p] = *(const float4*)(g_k + off);
            vreg[p] = *(const float4*)(g_v + off);
        }
    };
    auto stKV = [&](int bsel) {
        const uint32_t kb = AKV0 + bsel * ASTG;
#pragma unroll
        for (int p = 0; p < 8; ++p) {
            int r = sr + p * 8;
            uint32_t off = (uint32_t)(r * AROW + sc * 8);
            float4 f = kreg[p];
            float h0 = __bfloat162float(__float2bfloat16(f.x));
            float h1 = __bfloat162float(__float2bfloat16(f.y));
            float h2 = __bfloat162float(__float2bfloat16(f.z));
            float h3 = __bfloat162float(__float2bfloat16(f.w));
            *(uint2*)(sma + kb + off) = make_uint2(pack_bf2(h0, h1), pack_bf2(h2, h3));
            *(uint2*)(sma + kb + KTILE + off) =
                make_uint2(pack_bf2(f.x - h0, f.y - h1), pack_bf2(f.z - h2, f.w - h3));
            f = vreg[p];
            h0 = __bfloat162float(__float2bfloat16(f.x));
            h1 = __bfloat162float(__float2bfloat16(f.y));
            h2 = __bfloat162float(__float2bfloat16(f.z));
            h3 = __bfloat162float(__float2bfloat16(f.w));
            *(uint2*)(sma + kb + 2*KTILE + off) = make_uint2(pack_bf2(h0, h1), pack_bf2(h2, h3));
            *(uint2*)(sma + kb + 3*KTILE + off) =
                make_uint2(pack_bf2(f.x - h0, f.y - h1), pack_bf2(f.z - h2, f.w - h3));
        }
    };

    ldKV(st0);
    stKV(0);
    if (st0 + 1 <= stL) ldKV(st0 + 1);
    __syncthreads();

    float m_i[2] = {-1e30f, -1e30f}, l_i[2] = {0.f, 0.f};
    float ao[16][4];
#pragma unroll
    for (int t = 0; t < 16; ++t)
#pragma unroll
        for (int c = 0; c < 4; ++c) ao[t][c] = 0.f;

    for (int st = st0; st <= stL; ++st) {
        const int bsel = (st - st0) & 1;
        const uint32_t kb  = sb + AKV0 + bsel * ASTG;
        const uint32_t vhB = kb + 2*KTILE;
        const int s0 = st * 64;

        // ---- hoisted: stage NEXT KV into the idle buffer + prefetch st+2 ----
        // (safe: buffer bsel^1 was last read in step st-1, fenced by the
        //  end-of-step barrier; its ALU work overlaps the QK mma below)
        if (st < stL) stKV(bsel ^ 1);
        if (st + 2 <= stL) ldKV(st + 2);

        // ---- S = Q K^T (3-pass split, x4 K loads) ----
        float as[8][4];
#pragma unroll
        for (int nt = 0; nt < 8; ++nt)
#pragma unroll
            for (int c = 0; c < 4; ++c) as[nt][c] = 0.f;

#pragma unroll
        for (int kc = 0; kc < 8; ++kc) {
            uint32_t qa = sb + (row0 + (lane & 15)) * AROW + kc*32 + (lane >> 4) * 16;
            uint32_t qh[4], ql[4];
            LDSM4(qh, qa);
            LDSM4(ql, qa + QTILE);
#pragma unroll
            for (int ntp = 0; ntp < 4; ++ntp) {
                uint32_t ka = kb + (ntp*16 + (lane >> 4)*8 + (lane & 7)) * AROW
                            + kc*32 + ((lane >> 3) & 1) * 16;
                uint32_t kh4[4], kl4[4];
                LDSM4(kh4, ka);
                LDSM4(kl4, ka + KTILE);
#pragma unroll
                for (int j = 0; j < 2; ++j) {
                    const int nt = ntp*2 + j;
                    MMA16816(as[nt], qh, &kh4[2*j]);
                    MMA16816(as[nt], ql, &kh4[2*j]);
                    MMA16816(as[nt], qh, &kl4[2*j]);
                }
            }
        }

        // ---- softcap + mask + online softmax ----
        float scale_[2];
#pragma unroll
        for (int hf = 0; hf < 2; ++hf) {
            const int qrow = q0 + row0 + rg + hf*8;
            float rm = -1e30f;
#pragma unroll
            for (int nt = 0; nt < 8; ++nt)
#pragma unroll
                for (int cc = 0; cc < 2; ++cc) {
                    const int scol = s0 + nt*8 + tg*2 + cc;
                    float xx = softcap(as[nt][hf*2 + cc]);
                    const bool valid = (scol <= qrow) && (qrow - scol < CWIN);
                    xx = valid ? xx : -1e30f;
                    as[nt][hf*2 + cc] = xx;
                    rm = fmaxf(rm, xx);
                }
            rm = fmaxf(rm, __shfl_xor_sync(0xffffffffu, rm, 1));
            rm = fmaxf(rm, __shfl_xor_sync(0xffffffffu, rm, 2));

            const float mn = fmaxf(m_i[hf], rm);
            scale_[hf] = __expf(m_i[hf] - mn);
            m_i[hf] = mn;

            float sl = 0.f;
#pragma unroll
            for (int nt = 0; nt < 8; ++nt)
#pragma unroll
                for (int cc = 0; cc < 2; ++cc) {
                    float v = as[nt][hf*2 + cc];
                    float p = (v > -1e29f) ? __expf(v - mn) : 0.f;
                    as[nt][hf*2 + cc] = p;
                    sl += p;
                }
            sl += __shfl_xor_sync(0xffffffffu, sl, 1);
            sl += __shfl_xor_sync(0xffffffffu, sl, 2);
            l_i[hf] = l_i[hf] * scale_[hf] + sl;
        }
#pragma unroll
        for (int nt = 0; nt < 16; ++nt) {
            ao[nt][0] *= scale_[0]; ao[nt][1] *= scale_[0];
            ao[nt][2] *= scale_[1]; ao[nt][3] *= scale_[1];
        }

        // ---- O += P V (P split in regs; x4 trans V loads) ----
#pragma unroll
        for (int kc = 0; kc < 4; ++kc) {
            uint32_t ph[4], pl[4];
#pragma unroll
            for (int half = 0; half < 2; ++half) {
                const int nt = 2*kc + half;
                float p0 = as[nt][0], p1 = as[nt][1], p2 = as[nt][2], p3 = as[nt][3];
                float h0 = __bfloat162float(__float2bfloat16(p0));
                float h1 = __bfloat162float(__float2bfloat16(p1));
                float h2 = __bfloat162float(__float2bfloat16(p2));
                float h3 = __bfloat162float(__float2bfloat16(p3));
                ph[half*2 + 0] = pack_bf2(p0, p1);
                ph[half*2 + 1] = pack_bf2(p2, p3);
                pl[half*2 + 0] = pack_bf2(p0 - h0, p1 - h1);
                pl[half*2 + 1] = pack_bf2(p2 - h2, p3 - h3);
            }
#pragma unroll
            for (int ntp = 0; ntp < 8; ++ntp) {
                uint32_t va = vhB + (kc*16 + (lane & 15)) * AROW
                            + ntp*32 + (lane >> 4) * 16;
                uint32_t vh4[4], vl4[4];
                LDSM4T(vh4, va);
                LDSM4T(vl4, va + KTILE);
#pragma unroll
                for (int j = 0; j < 2; ++j) {
                    const int nt = ntp*2 + j;
                    MMA16816(ao[nt], ph, &vh4[2*j]);
                    MMA16816(ao[nt], pl, &vh4[2*j]);
                    MMA16816(ao[nt], ph, &vl4[2*j]);
                }
            }
        }

        __syncthreads();
    }

#pragma unroll
    for (int hf = 0; hf < 2; ++hf) {
        const int qrow = q0 + row0 + rg + hf*8;
        const float inv = 1.0f / l_i[hf];
        float* o = g_enc + ((size_t)(b*CT + qrow) * CN + n) * CH;
#pragma unroll
        for (int nt = 0; nt < 16; ++nt)
            *(float2*)(o + nt*8 + tg*2) =
                make_float2(ao[nt][hf*2 + 0] * inv, ao[nt][hf*2 + 1] * inv);
    }
}

// ---------------------------------------------------------------------------
extern "C" void kernel_launch(void* const* d_in, const int* in_sizes, int n_in,
                              void* d_out, int out_size)
{
    const float* x   = (const float*)d_in[0];
    const float* wq  = (const float*)d_in[1];
    const float* wkv = (const float*)d_in[2];
    const float* wo  = (const float*)d_in[3];
    const int*   seg = (const int*)d_in[4];
    float* out = (float*)d_out;

    cudaFuncSetAttribute(attn_kernel,
                         cudaFuncAttributeMaxDynamicSharedMemorySize, ATT_SMEM);
    cudaFuncSetAttribute(qkv_kernel,
                         cudaFuncAttributeMaxDynamicSharedMemorySize, GEM_SMEM);
    cudaFuncSetAttribute(oproj_kernel,
                         cudaFuncAttributeMaxDynamicSharedMemorySize, GEM_SMEM);

    rope_init_kernel<<<1, 64>>>();
    qkv_kernel<<<dim3(32, 32), 256, GEM_SMEM>>>(x, wq, wkv);
    rope_kernel<<<(ROPE_QC + ROPE_KC + 255)/256, 256>>>(seg);
    attn_kernel<<<dim3(CT/128, CN, CB), 256, ATT_SMEM>>>();
    oproj_kernel<<<dim3(32, 16), 256, GEM_SMEM>>>(wo, out);
}

// round 16
// speedup vs baseline: 1.1016x; 1.0016x over previous
#include <cuda_runtime.h>
#include <cuda_bf16.h>
#include <math.h>
#include <stdint.h>

// Problem constants
#define CB 2
#define CT 2048
#define CD 2048
#define CN 16
#define CK 8
#define CH 128
#define CWIN 1024
#define CBT (CB*CT)

#define ROPE_QC (CB*CT*CN*64)
#define ROPE_KC (CB*CT*CK*64)

// Scratch (device globals; the exact 100.7MB set proven to pass the guard)
__device__ float g_q  [CBT*CN*CH];   // [B,T,N,H]
__device__ float g_k  [CBT*CK*CH];
__device__ float g_v  [CBT*CK*CH];
__device__ float g_enc[CBT*CN*CH];
__device__ float g_ts [64];

// ---------------------------------------------------------------------------
__global__ void rope_init_kernel() {
    int i = threadIdx.x;
    if (i < 64) g_ts[i] = (float)pow(10000.0, (double)i / 64.0);
}

__device__ __forceinline__ uint32_t pack_bf2(float x, float y) {
    __nv_bfloat162 h = __floats2bfloat162_rn(x, y);
    return *(uint32_t*)&h;
}

#define LDSM4(r, addr) \
    asm volatile("ldmatrix.sync.aligned.m8n8.x4.shared.b16 {%0,%1,%2,%3}, [%4];\n" \
        : "=r"((r)[0]), "=r"((r)[1]), "=r"((r)[2]), "=r"((r)[3]) : "r"(addr))
#define LDSM2T(r, addr) \
    asm volatile("ldmatrix.sync.aligned.m8n8.x2.trans.shared.b16 {%0,%1}, [%2];\n" \
        : "=r"((r)[0]), "=r"((r)[1]) : "r"(addr))
#define LDSM4T(r, addr) \
    asm volatile("ldmatrix.sync.aligned.m8n8.x4.trans.shared.b16 {%0,%1,%2,%3}, [%4];\n" \
        : "=r"((r)[0]), "=r"((r)[1]), "=r"((r)[2]), "=r"((r)[3]) : "r"(addr))
#define MMA16816(d, a, b) \
    asm volatile("mma.sync.aligned.m16n8k16.row.col.f32.bf16.bf16.f32 " \
        "{%0,%1,%2,%3}, {%4,%5,%6,%7}, {%8,%9}, {%0,%1,%2,%3};\n" \
        : "+f"((d)[0]), "+f"((d)[1]), "+f"((d)[2]), "+f"((d)[3]) \
        : "r"((a)[0]), "r"((a)[1]), "r"((a)[2]), "r"((a)[3]), "r"((b)[0]), "r"((b)[1]))

// ---------------------------------------------------------------------------
// Split-bf16 tensor-core GEMM — pass-major mma emission (dependency spacing)
// ---------------------------------------------------------------------------
#define A_STR 40
#define B_STR 136
#define A_TILE (128*A_STR)
#define B_TILE (32*B_STR)
#define GEM_SMEM ((4*A_TILE + 4*B_TILE) * 2)

__device__ __forceinline__ void gemm_split_128x128(
    const float* __restrict__ A, int lda,
    const float* __restrict__ B, int ldb,
    float* __restrict__ C, int ldc, int Kd)
{
    extern __shared__ __nv_bfloat16 smg[];
    __nv_bfloat16* const sA = smg;
    __nv_bfloat16* const sB = smg + 4 * A_TILE;
    const uint32_t sAb = (uint32_t)__cvta_generic_to_shared(sA);
    const uint32_t sBb = (uint32_t)__cvta_generic_to_shared(sB);

    const int tid  = threadIdx.x;
    const int lane = tid & 31;
    const int wid  = tid >> 5;
    const int wm   = wid >> 2;
    const int wn   = wid & 3;

    const int ar = tid >> 1, ac = (tid & 1) * 4;
    const int br = tid >> 3, bc = (tid & 7) * 4;

    const float* Ap = A + (size_t)ar * lda + ac;
    const float* Bp = B + (size_t)br * ldb + bc;

    float acc[4][4][4];
#pragma unroll
    for (int a = 0; a < 4; ++a)
#pragma unroll
        for (int b = 0; b < 4; ++b)
#pragma unroll
            for (int c = 0; c < 4; ++c) acc[a][b][c] = 0.f;

    float4 av[4], bv[4];
#pragma unroll
    for (int q = 0; q < 4; ++q) {
        av[q] = *(const float4*)(Ap + q * 8);
        bv[q] = *(const float4*)(Bp + q * 32);
    }

    const int nIter = Kd >> 5;
    for (int it = 0; it < nIter; ++it) {
        const int cur = it & 1;
        __nv_bfloat16* aHi = sA + (2 * cur)     * A_TILE;
        __nv_bfloat16* aLo = sA + (2 * cur + 1) * A_TILE;
        __nv_bfloat16* bHi = sB + (2 * cur)     * B_TILE;
        __nv_bfloat16* bLo = sB + (2 * cur + 1) * B_TILE;

#pragma unroll
        for (int q = 0; q < 4; ++q) {
            float a0 = av[q].x, a1 = av[q].y, a2 = av[q].z, a3 = av[q].w;
            float h0 = __bfloat162float(__float2bfloat16(a0));
            float h1 = __bfloat162float(__float2bfloat16(a1));
            float h2 = __bfloat162float(__float2bfloat16(a2));
            float h3 = __bfloat162float(__float2bfloat16(a3));
            uint2 H = make_uint2(pack_bf2(h0, h1), pack_bf2(h2, h3));
            uint2 L = make_uint2(pack_bf2(a0 - h0, a1 - h1), pack_bf2(a2 - h2, a3 - h3));
            *(uint2*)(aHi + ar * A_STR + ac + q * 8) = H;
            *(uint2*)(aLo + ar * A_STR + ac + q * 8) = L;

            float b0 = bv[q].x, b1 = bv[q].y, b2 = bv[q].z, b3 = bv[q].w;
            float g0 = __bfloat162float(__float2bfloat16(b0));
            float g1 = __bfloat162float(__float2bfloat16(b1));
            float g2 = __bfloat162float(__float2bfloat16(b2));
            float g3 = __bfloat162float(__float2bfloat16(b3));
            H = make_uint2(pack_bf2(g0, g1), pack_bf2(g2, g3));
            L = make_uint2(pack_bf2(b0 - g0, b1 - g1), pack_bf2(b2 - g2, b3 - g3));
            *(uint2*)(bHi + br * B_STR + bc + q * 32) = H;
            *(uint2*)(bLo + br * B_STR + bc + q * 32) = L;
        }
        __syncthreads();

        if (it + 1 < nIter) {
            const float* An = Ap + (it + 1) * 32;
            const float* Bn = Bp + (size_t)(it + 1) * 32 * ldb;
#pragma unroll
            for (int q = 0; q < 4; ++q) {
                av[q] = *(const float4*)(An + q * 8);
                bv[q] = *(const float4*)(Bn + q * 32);
            }
        }

        const uint32_t aHiB = sAb + (2 * cur)     * A_TILE * 2;
        const uint32_t aLoB = sAb + (2 * cur + 1) * A_TILE * 2;
        const uint32_t bHiB = sBb + (2 * cur)     * B_TILE * 2;
        const uint32_t bLoB = sBb + (2 * cur + 1) * B_TILE * 2;

#pragma unroll
        for (int ks = 0; ks < 32; ks += 16) {
            uint32_t bhi[4][2], blo[4][2];
#pragma unroll
            for (int nt = 0; nt < 4; ++nt) {
                uint32_t off = (ks + (lane & 15)) * (B_STR * 2) + (wn * 32 + nt * 8) * 2;
                LDSM2T(bhi[nt], bHiB + off);
                LDSM2T(blo[nt], bLoB + off);
            }
            uint32_t ahi[4][4], alo[4][4];
#pragma unroll
            for (int mt = 0; mt < 4; ++mt) {
                int row = wm * 64 + mt * 16 + (lane & 15);
                uint32_t off = row * (A_STR * 2) + ks * 2 + (lane >> 4) * 16;
                LDSM4(ahi[mt], aHiB + off);
                LDSM4(alo[mt], aLoB + off);
            }
            // pass-major: 16 independent mmas between same-acc reuse
#pragma unroll
            for (int mt = 0; mt < 4; ++mt)
#pragma unroll
                for (int nt = 0; nt < 4; ++nt)
                    MMA16816(acc[mt][nt], ahi[mt], bhi[nt]);
#pragma unroll
            for (int mt = 0; mt < 4; ++mt)
#pragma unroll
                for (int nt = 0; nt < 4; ++nt)
                    MMA16816(acc[mt][nt], alo[mt], bhi[nt]);
#pragma unroll
            for (int mt = 0; mt < 4; ++mt)
#pragma unroll
                for (int nt = 0; nt < 4; ++nt)
                    MMA16816(acc[mt][nt], ahi[mt], blo[nt]);
        }
    }

    const int rg = lane >> 2, tg = lane & 3;
#pragma unroll
    for (int mt = 0; mt < 4; ++mt)
#pragma unroll
        for (int nt = 0; nt < 4; ++nt) {
            int r = wm * 64 + mt * 16 + rg;
            int c = wn * 32 + nt * 8 + tg * 2;
            *(float2*)&C[(size_t)r * ldc + c]       = make_float2(acc[mt][nt][0], acc[mt][nt][1]);
            *(float2*)&C[(size_t)(r + 8) * ldc + c] = make_float2(acc[mt][nt][2], acc[mt][nt][3]);
        }
}

// ---------------------------------------------------------------------------
__global__ __launch_bounds__(256, 1) void qkv_kernel(
    const float* __restrict__ x,
    const float* __restrict__ wq,
    const float* __restrict__ wkv)
{
    const int m0 = blockIdx.x * 128;
    const int h  = blockIdx.y;
    const float* A = x + (size_t)m0 * CD;
    const float* W;
    float* C; int ldc;
    if (h < CN) {
        W = wq + (size_t)h * CD * CH;
        C = g_q + (size_t)m0 * CN * CH + h * CH; ldc = CN * CH;
    } else if (h < CN + CK) {
        const int kk = h - CN;
        W = wkv + (size_t)kk * CD * CH;
        C = g_k + (size_t)m0 * CK * CH + kk * CH; ldc = CK * CH;
    } else {
        const int kk = h - CN - CK;
        W = wkv + (size_t)(CK + kk) * CD * CH;
        C = g_v + (size_t)m0 * CK * CH + kk * CH; ldc = CK * CH;
    }
    gemm_split_128x128(A, CD, W, CH, C, ldc, CD);
}

__global__ __launch_bounds__(256, 1) void oproj_kernel(
    const float* __restrict__ wo, float* __restrict__ out)
{
    const int m0 = blockIdx.x * 128;
    const int n0 = blockIdx.y * 128;
    gemm_split_128x128(g_enc + (size_t)m0 * (CN*CH), CN*CH,
                       wo + n0, CD,
                       out + (size_t)m0 * CD + n0, CD, CN*CH);
}

// ---------------------------------------------------------------------------
__global__ __launch_bounds__(256) void rope_kernel(const int* __restrict__ seg)
{
    int idx = blockIdx.x * blockDim.x + threadIdx.x;
    if (idx >= ROPE_QC + ROPE_KC) return;

    float* buf; int heads; float scal; int lidx;
    if (idx < ROPE_QC) {
        buf = g_q; heads = CN; scal = 0.08838834764831845f; lidx = idx;
    } else {
        buf = g_k; heads = CK; scal = 1.0f; lidx = idx - ROPE_QC;
    }
    const int i    = lidx & 63;
    const int rest = lidx >> 6;
    const int bt   = rest / heads;
    const int pos  = seg[bt];

    float ts = g_ts[i];
    float ang = (float)pos / ts;
    float s, c;
    sincosf(ang, &s, &c);

    float* p = buf + (size_t)rest * CH;
    float x1 = p[i];
    float x2 = p[i + 64];
    p[i]      = (x1 * c - x2 * s) * scal;
    p[i + 64] = (x2 * c + x1 * s) * scal;
}

// ---------------------------------------------------------------------------
__device__ __forceinline__ float softcap(float v)
{
    float x = v * (1.0f / 50.0f);
    float ax = fabsf(x);
    if (ax < 0.25f) {
        float x2 = x * x;
        float t = x * (1.0f + x2 * (-1.0f/3.0f + x2 * (2.0f/15.0f + x2 * (-17.0f/315.0f))));
        return t * 50.0f;
    }
    return tanhf(x) * 50.0f;
}

// ---------------------------------------------------------------------------
// Tensor-core flash attention — pass-major mma groups of 4 nt.
// ---------------------------------------------------------------------------
#define AROW 272
#define QTILE (128*AROW)
#define KTILE (64*AROW)
#define ASTG  (4*KTILE)
#define AKV0  (2*QTILE)
#define ATT_SMEM (AKV0 + 2*ASTG)

__global__ __launch_bounds__(256, 1) void attn_kernel()
{
    extern __shared__ char sma[];
    const uint32_t sb = (uint32_t)__cvta_generic_to_shared(sma);

    const int tid = threadIdx.x, lane = tid & 31, w = tid >> 5;
    const int rg = lane >> 2, tg = lane & 3;
    const int qt = blockIdx.x, n = blockIdx.y, b = blockIdx.z;
    const int kk = n >> 1;
    const int q0 = qt * 128;
    const int row0 = w * 16;

#pragma unroll
    for (int p = 0; p < 16; ++p) {
        int idx = tid + p * 256;
        int r = idx >> 5, c4 = idx & 31;
        float4 f = *(const float4*)(g_q +
            ((size_t)(b*CT + q0 + r) * CN + n) * CH + c4 * 4);
        float h0 = __bfloat162float(__float2bfloat16(f.x));
        float h1 = __bfloat162float(__float2bfloat16(f.y));
        float h2 = __bfloat162float(__float2bfloat16(f.z));
        float h3 = __bfloat162float(__float2bfloat16(f.w));
        uint32_t off = (uint32_t)(r * AROW + c4 * 8);
        *(uint2*)(sma + off)         = make_uint2(pack_bf2(h0, h1), pack_bf2(h2, h3));
        *(uint2*)(sma + QTILE + off) = make_uint2(pack_bf2(f.x - h0, f.y - h1),
                                                  pack_bf2(f.z - h2, f.w - h3));
    }

    int st0 = q0 - (CWIN - 1); if (st0 < 0) st0 = 0; st0 >>= 6;
    const int stL = (q0 + 127) >> 6;

    float4 kreg[8], vreg[8];
    const int sr = tid >> 5, sc = tid & 31;

    auto ldKV = [&](int st) {
        const int s0 = st * 64;
#pragma unroll
        for (int p = 0; p < 8; ++p) {
            int r = sr + p * 8;
            size_t off = ((size_t)(b*CT + s0 + r) * CK + kk) * CH + sc * 4;
            kreg[p] = *(const float4*)(g_k + off);
            vreg[p] = *(const float4*)(g_v + off);
        }
    };
    auto stKV = [&](int bsel) {
        const uint32_t kb = AKV0 + bsel * ASTG;
#pragma unroll
        for (int p = 0; p < 8; ++p) {
            int r = sr + p * 8;
            uint32_t off = (uint32_t)(r * AROW + sc * 8);
            float4 f = kreg[p];
            float h0 = __bfloat162float(__float2bfloat16(f.x));
            float h1 = __bfloat162float(__float2bfloat16(f.y));
            float h2 = __bfloat162float(__float2bfloat16(f.z));
            float h3 = __bfloat162float(__float2bfloat16(f.w));
            *(uint2*)(sma + kb + off) = make_uint2(pack_bf2(h0, h1), pack_bf2(h2, h3));
            *(uint2*)(sma + kb + KTILE + off) =
                make_uint2(pack_bf2(f.x - h0, f.y - h1), pack_bf2(f.z - h2, f.w - h3));
            f = vreg[p];
            h0 = __bfloat162float(__float2bfloat16(f.x));
            h1 = __bfloat162float(__float2bfloat16(f.y));
            h2 = __bfloat162float(__float2bfloat16(f.z));
            h3 = __bfloat162float(__float2bfloat16(f.w));
            *(uint2*)(sma + kb + 2*KTILE + off) = make_uint2(pack_bf2(h0, h1), pack_bf2(h2, h3));
            *(uint2*)(sma + kb + 3*KTILE + off) =
                make_uint2(pack_bf2(f.x - h0, f.y - h1), pack_bf2(f.z - h2, f.w - h3));
        }
    };

    ldKV(st0);
    stKV(0);
    if (st0 + 1 <= stL) ldKV(st0 + 1);
    __syncthreads();

    float m_i[2] = {-1e30f, -1e30f}, l_i[2] = {0.f, 0.f};
    float ao[16][4];
#pragma unroll
    for (int t = 0; t < 16; ++t)
#pragma unroll
        for (int c = 0; c < 4; ++c) ao[t][c] = 0.f;

    for (int st = st0; st <= stL; ++st) {
        const int bsel = (st - st0) & 1;
        const uint32_t kb  = sb + AKV0 + bsel * ASTG;
        const uint32_t vhB = kb + 2*KTILE;
        const int s0 = st * 64;

        // ---- hoisted staging for next step (overlaps QK mma below) ----
        if (st < stL) stKV(bsel ^ 1);
        if (st + 2 <= stL) ldKV(st + 2);

        // ---- S = Q K^T (pass-major in groups of 4 nt) ----
        float as[8][4];
#pragma unroll
        for (int nt = 0; nt < 8; ++nt)
#pragma unroll
            for (int c = 0; c < 4; ++c) as[nt][c] = 0.f;

#pragma unroll
        for (int kc = 0; kc < 8; ++kc) {
            uint32_t qa = sb + (row0 + (lane & 15)) * AROW + kc*32 + (lane >> 4) * 16;
            uint32_t qh[4], ql[4];
            LDSM4(qh, qa);
            LDSM4(ql, qa + QTILE);
#pragma unroll
            for (int np = 0; np < 2; ++np) {
                uint32_t kh4[2][4], kl4[2][4];
#pragma unroll
                for (int t = 0; t < 2; ++t) {
                    const int ntp = np*2 + t;
                    uint32_t ka = kb + (ntp*16 + (lane >> 4)*8 + (lane & 7)) * AROW
                                + kc*32 + ((lane >> 3) & 1) * 16;
                    LDSM4(kh4[t], ka);
                    LDSM4(kl4[t], ka + KTILE);
                }
#pragma unroll
                for (int t = 0; t < 2; ++t)
#pragma unroll
                    for (int j = 0; j < 2; ++j)
                        MMA16816(as[np*4 + t*2 + j], qh, &kh4[t][2*j]);
#pragma unroll
                for (int t = 0; t < 2; ++t)
#pragma unroll
                    for (int j = 0; j < 2; ++j)
                        MMA16816(as[np*4 + t*2 + j], ql, &kh4[t][2*j]);
#pragma unroll
                for (int t = 0; t < 2; ++t)
#pragma unroll
                    for (int j = 0; j < 2; ++j)
                        MMA16816(as[np*4 + t*2 + j], qh, &kl4[t][2*j]);
            }
        }

        // ---- softcap + mask + online softmax ----
        float scale_[2];
#pragma unroll
        for (int hf = 0; hf < 2; ++hf) {
            const int qrow = q0 + row0 + rg + hf*8;
            float rm = -1e30f;
#pragma unroll
            for (int nt = 0; nt < 8; ++nt)
#pragma unroll
                for (int cc = 0; cc < 2; ++cc) {
                    const int scol = s0 + nt*8 + tg*2 + cc;
                    float xx = softcap(as[nt][hf*2 + cc]);
                    const bool valid = (scol <= qrow) && (qrow - scol < CWIN);
                    xx = valid ? xx : -1e30f;
                    as[nt][hf*2 + cc] = xx;
                    rm = fmaxf(rm, xx);
                }
            rm = fmaxf(rm, __shfl_xor_sync(0xffffffffu, rm, 1));
            rm = fmaxf(rm, __shfl_xor_sync(0xffffffffu, rm, 2));

            const float mn = fmaxf(m_i[hf], rm);
            scale_[hf] = __expf(m_i[hf] - mn);
            m_i[hf] = mn;

            float sl = 0.f;
#pragma unroll
            for (int nt = 0; nt < 8; ++nt)
#pragma unroll
                for (int cc = 0; cc < 2; ++cc) {
                    float v = as[nt][hf*2 + cc];
                    float p = (v > -1e29f) ? __expf(v - mn) : 0.f;
                    as[nt][hf*2 + cc] = p;
                    sl += p;
                }
            sl += __shfl_xor_sync(0xffffffffu, sl, 1);
            sl += __shfl_xor_sync(0xffffffffu, sl, 2);
            l_i[hf] = l_i[hf] * scale_[hf] + sl;
        }
#pragma unroll
        for (int nt = 0; nt < 16; ++nt) {
            ao[nt][0] *= scale_[0]; ao[nt][1] *= scale_[0];
            ao[nt][2] *= scale_[1]; ao[nt][3] *= scale_[1];
        }

        // ---- O += P V (pass-major in groups of 4 nt) ----
#pragma unroll
        for (int kc = 0; kc < 4; ++kc) {
            uint32_t ph[4], pl[4];
#pragma unroll
            for (int half = 0; half < 2; ++half) {
                const int nt = 2*kc + half;
                float p0 = as[nt][0], p1 = as[nt][1], p2 = as[nt][2], p3 = as[nt][3];
                float h0 = __bfloat162float(__float2bfloat16(p0));
                float h1 = __bfloat162float(__float2bfloat16(p1));
                float h2 = __bfloat162float(__float2bfloat16(p2));
                float h3 = __bfloat162float(__float2bfloat16(p3));
                ph[half*2 + 0] = pack_bf2(p0, p1);
                ph[half*2 + 1] = pack_bf2(p2, p3);
                pl[half*2 + 0] = pack_bf2(p0 - h0, p1 - h1);
                pl[half*2 + 1] = pack_bf2(p2 - h2, p3 - h3);
            }
#pragma unroll
            for (int np = 0; np < 4; ++np) {
                uint32_t vh4[2][4], vl4[2][4];
#pragma unroll
                for (int t = 0; t < 2; ++t) {
                    const int ntp = np*2 + t;
                    uint32_t va = vhB + (kc*16 + (lane & 15)) * AROW
                                + ntp*32 + (lane >> 4) * 16;
                    LDSM4T(vh4[t], va);
                    LDSM4T(vl4[t], va + KTILE);
                }
#pragma unroll
                for (int t = 0; t < 2; ++t)
#pragma unroll
                    for (int j = 0; j < 2; ++j)
                        MMA16816(ao[np*4 + t*2 + j], ph, &vh4[t][2*j]);
#pragma unroll
                for (int t = 0; t < 2; ++t)
#pragma unroll
                    for (int j = 0; j < 2; ++j)
                        MMA16816(ao[np*4 + t*2 + j], pl, &vh4[t][2*j]);
#pragma unroll
                for (int t = 0; t < 2; ++t)
#pragma unroll
                    for (int j = 0; j < 2; ++j)
                        MMA16816(ao[np*4 + t*2 + j], ph, &vl4[t][2*j]);
            }
        }

        __syncthreads();
    }

#pragma unroll
    for (int hf = 0; hf < 2; ++hf) {
        const int qrow = q0 + row0 + rg + hf*8;
        const float inv = 1.0f / l_i[hf];
        float* o = g_enc + ((size_t)(b*CT + qrow) * CN + n) * CH;
#pragma unroll
        for (int nt = 0; nt < 16; ++nt)
            *(float2*)(o + nt*8 + tg*2) =
                make_float2(ao[nt][hf*2 + 0] * inv, ao[nt][hf*2 + 1] * inv);
    }
}

// ---------------------------------------------------------------------------
extern "C" void kernel_launch(void* const* d_in, const int* in_sizes, int n_in,
                              void* d_out, int out_size)
{
    const float* x   = (const float*)d_in[0];
    const float* wq  = (const float*)d_in[1];
    const float* wkv = (const float*)d_in[2];
    const float* wo  = (const float*)d_in[3];
    const int*   seg = (const int*)d_in[4];
    float* out = (float*)d_out;

    cudaFuncSetAttribute(attn_kernel,
                         cudaFuncAttributeMaxDynamicSharedMemorySize, ATT_SMEM);
    cudaFuncSetAttribute(qkv_kernel,
                         cudaFuncAttributeMaxDynamicSharedMemorySize, GEM_SMEM);
    cudaFuncSetAttribute(oproj_kernel,
                         cudaFuncAttributeMaxDynamicSharedMemorySize, GEM_SMEM);

    rope_init_kernel<<<1, 64>>>();
    qkv_kernel<<<dim3(32, 32), 256, GEM_SMEM>>>(x, wq, wkv);
    rope_kernel<<<(ROPE_QC + ROPE_KC + 255)/256, 256>>>(seg);
    attn_kernel<<<dim3(CT/128, CN, CB), 256, ATT_SMEM>>>();
    oproj_kernel<<<dim3(32, 16), 256, GEM_SMEM>>>(wo, out);
}

// round 17
// speedup vs baseline: 1.1211x; 1.0177x over previous
#include <cuda_runtime.h>
#include <cuda_bf16.h>
#include <math.h>
#include <stdint.h>

// Problem constants
#define CB 2
#define CT 2048
#define CD 2048
#define CN 16
#define CK 8
#define CH 128
#define CWIN 1024
#define CBT (CB*CT)

#define ROPE_QC (CB*CT*CN*64)
#define ROPE_KC (CB*CT*CK*64)

// Scratch (device globals; the exact 100.7MB set proven to pass the guard)
__device__ float g_q  [CBT*CN*CH];   // [B,T,N,H]; post-attn reused for wo3 hi/lo
__device__ float g_k  [CBT*CK*CH];
__device__ float g_v  [CBT*CK*CH];
__device__ float g_enc[CBT*CN*CH];   // pre-attn: w3 hi/lo; post-attn: encoded fp32
__device__ float g_ts [64];

// Views into free buffers for pre-split weights
#define W3_ELEMS (32u*2048u*128u)          // 8.39M bf16 per component
#define WO3_ELEMS (2048u*2048u)

// ---------------------------------------------------------------------------
__global__ void rope_init_kernel() {
    int i = threadIdx.x;
    if (i < 64) g_ts[i] = (float)pow(10000.0, (double)i / 64.0);
}

__device__ __forceinline__ uint32_t pack_bf2(float x, float y) {
    __nv_bfloat162 h = __floats2bfloat162_rn(x, y);
    return *(uint32_t*)&h;
}
__device__ __forceinline__ void cp16(uint32_t dst, const void* src) {
    asm volatile("cp.async.cg.shared.global [%0], [%1], 16;\n" :: "r"(dst), "l"(src));
}

#define LDSM4(r, addr) \
    asm volatile("ldmatrix.sync.aligned.m8n8.x4.shared.b16 {%0,%1,%2,%3}, [%4];\n" \
        : "=r"((r)[0]), "=r"((r)[1]), "=r"((r)[2]), "=r"((r)[3]) : "r"(addr))
#define LDSM2T(r, addr) \
    asm volatile("ldmatrix.sync.aligned.m8n8.x2.trans.shared.b16 {%0,%1}, [%2];\n" \
        : "=r"((r)[0]), "=r"((r)[1]) : "r"(addr))
#define LDSM4T(r, addr) \
    asm volatile("ldmatrix.sync.aligned.m8n8.x4.trans.shared.b16 {%0,%1,%2,%3}, [%4];\n" \
        : "=r"((r)[0]), "=r"((r)[1]), "=r"((r)[2]), "=r"((r)[3]) : "r"(addr))
#define MMA16816(d, a, b) \
    asm volatile("mma.sync.aligned.m16n8k16.row.col.f32.bf16.bf16.f32 " \
        "{%0,%1,%2,%3}, {%4,%5,%6,%7}, {%8,%9}, {%0,%1,%2,%3};\n" \
        : "+f"((d)[0]), "+f"((d)[1]), "+f"((d)[2]), "+f"((d)[3]) \
        : "r"((a)[0]), "r"((a)[1]), "r"((a)[2]), "r"((a)[3]), "r"((b)[0]), "r"((b)[1]))

// ---------------------------------------------------------------------------
// One-time weight splits
// ---------------------------------------------------------------------------
__global__ __launch_bounds__(256) void split_w_kernel(
    const float* __restrict__ wq, const float* __restrict__ wkv)
{
    __nv_bfloat16* w3h = (__nv_bfloat16*)g_enc;
    __nv_bfloat16* w3l = w3h + W3_ELEMS;
    unsigned idx = blockIdx.x * 256 + threadIdx.x;
    if (idx >= W3_ELEMS) return;
    unsigned t = idx >> 18;                       // tile 0..31
    float v = (t < 16) ? wq[idx] : wkv[idx - (16u << 18)];
    __nv_bfloat16 hi = __float2bfloat16(v);
    w3h[idx] = hi;
    w3l[idx] = __float2bfloat16(v - __bfloat162float(hi));
}

__global__ __launch_bounds__(256) void split_wo_kernel(const float* __restrict__ wo)
{
    __nv_bfloat16* wo3h = (__nv_bfloat16*)g_q;
    __nv_bfloat16* wo3l = wo3h + WO3_ELEMS;
    unsigned idx = blockIdx.x * 256 + threadIdx.x;
    if (idx >= WO3_ELEMS) return;
    float v = wo[idx];
    __nv_bfloat16 hi = __float2bfloat16(v);
    wo3h[idx] = hi;
    wo3l[idx] = __float2bfloat16(v - __bfloat162float(hi));
}

// ---------------------------------------------------------------------------
// Wide split-bf16 GEMM: C[128][256] = A_f32[128][Kd] * B  (B pre-split bf16,
// two 128-col tiles, staged via cp.async). A split in-kernel as before.
// 8 warps (2m x 4n), warp tile 64x64. One __syncthreads per BK=32 iter.
// ---------------------------------------------------------------------------
#define A_STR 40
#define A_TILE (128*A_STR)                 // bf16 elems
#define B2_ROW 136                         // bf16 elems per B row (128+8 pad)
#define B2_TILE (32*B2_ROW)                // 4352 elems = 8704 B
#define G2_BOFF (4*A_TILE*2)               // 40960 B
#define GEM2_SMEM (G2_BOFF + 8*B2_TILE*2)  // 110592 B

__device__ __forceinline__ void gemm2(
    const float* __restrict__ A, int lda,
    const __nv_bfloat16* __restrict__ B0h, const __nv_bfloat16* __restrict__ B0l,
    const __nv_bfloat16* __restrict__ B1h, const __nv_bfloat16* __restrict__ B1l,
    int ldb,
    float* __restrict__ C0, float* __restrict__ C1, int ldc, int Kd)
{
    extern __shared__ char smg2[];
    const uint32_t sb = (uint32_t)__cvta_generic_to_shared(smg2);

    const int tid  = threadIdx.x;
    const int lane = tid & 31;
    const int wid  = tid >> 5;
    const int wm   = wid >> 2;        // 0..1
    const int wn   = wid & 3;         // 0..3
    const int btile = wn >> 1;        // which B tile this warp reads
    const int bcol0 = (wn & 1) * 64;  // col base within the tile

    const int ar = tid >> 1, ac = (tid & 1) * 4;
    const float* Ap = A + (size_t)ar * lda + ac;

    const __nv_bfloat16* bsrc[4] = { B0h, B0l, B1h, B1l };

    float acc[4][8][4];
#pragma unroll
    for (int a = 0; a < 4; ++a)
#pragma unroll
        for (int b = 0; b < 8; ++b)
#pragma unroll
            for (int c = 0; c < 4; ++c) acc[a][b][c] = 0.f;

    // B staging via cp.async: 2048 16B-chunks per iter (8 per thread)
    auto stageB = [&](int it, int buf) {
        const int k0 = it * 32;
#pragma unroll
        for (int j = 0; j < 8; ++j) {
            int id = tid + j * 256;            // 0..2047
            int c16 = id & 15;
            int r   = (id >> 4) & 31;
            int tc  = id >> 9;                 // 0..3 = (tile<<1)|comp
            uint32_t dst = sb + G2_BOFF + (uint32_t)(buf * 4 + tc) * (B2_TILE * 2)
                         + r * (B2_ROW * 2) + c16 * 16;
            cp16(dst, bsrc[tc] + (size_t)(k0 + r) * ldb + c16 * 8);
        }
        asm volatile("cp.async.commit_group;\n");
    };

    float4 av[4];
#pragma unroll
    for (int q = 0; q < 4; ++q) av[q] = *(const float4*)(Ap + q * 8);

    stageB(0, 0);

    const int nIter = Kd >> 5;
    for (int it = 0; it < nIter; ++it) {
        const int cur = it & 1;
        __nv_bfloat16* aHi = (__nv_bfloat16*)smg2 + (2 * cur)     * A_TILE;
        __nv_bfloat16* aLo = (__nv_bfloat16*)smg2 + (2 * cur + 1) * A_TILE;

        // split + store A slice
#pragma unroll
        for (int q = 0; q < 4; ++q) {
            float a0 = av[q].x, a1 = av[q].y, a2 = av[q].z, a3 = av[q].w;
            float h0 = __bfloat162float(__float2bfloat16(a0));
            float h1 = __bfloat162float(__float2bfloat16(a1));
            float h2 = __bfloat162float(__float2bfloat16(a2));
            float h3 = __bfloat162float(__float2bfloat16(a3));
            *(uint2*)(aHi + ar * A_STR + ac + q * 8) =
                make_uint2(pack_bf2(h0, h1), pack_bf2(h2, h3));
            *(uint2*)(aLo + ar * A_STR + ac + q * 8) =
                make_uint2(pack_bf2(a0 - h0, a1 - h1), pack_bf2(a2 - h2, a3 - h3));
        }
        asm volatile("cp.async.wait_group 0;\n");
        __syncthreads();

        if (it + 1 < nIter) {
            stageB(it + 1, cur ^ 1);
            const float* An = Ap + (it + 1) * 32;
#pragma unroll
            for (int q = 0; q < 4; ++q) av[q] = *(const float4*)(An + q * 8);
        }

        const uint32_t aHiB = sb + (2 * cur)     * A_TILE * 2;
        const uint32_t aLoB = sb + (2 * cur + 1) * A_TILE * 2;
        const uint32_t bHiB = sb + G2_BOFF + (uint32_t)(cur * 4 + btile * 2)     * (B2_TILE * 2);
        const uint32_t bLoB = sb + G2_BOFF + (uint32_t)(cur * 4 + btile * 2 + 1) * (B2_TILE * 2);

#pragma unroll
        for (int ks = 0; ks < 32; ks += 16) {
            uint32_t bhi[8][2], blo[8][2];
#pragma unroll
            for (int nt = 0; nt < 8; ++nt) {
                uint32_t off = (ks + (lane & 15)) * (B2_ROW * 2) + (bcol0 + nt * 8) * 2;
                LDSM2T(bhi[nt], bHiB + off);
                LDSM2T(blo[nt], bLoB + off);
            }
#pragma unroll
            for (int mt = 0; mt < 4; ++mt) {
                int row = wm * 64 + mt * 16 + (lane & 15);
                uint32_t off = row * (A_STR * 2) + ks * 2 + (lane >> 4) * 16;
                uint32_t ahi[4], alo[4];
                LDSM4(ahi, aHiB + off);
                LDSM4(alo, aLoB + off);
#pragma unroll
                for (int nt = 0; nt < 8; ++nt) MMA16816(acc[mt][nt], ahi, bhi[nt]);
#pragma unroll
                for (int nt = 0; nt < 8; ++nt) MMA16816(acc[mt][nt], alo, bhi[nt]);
#pragma unroll
                for (int nt = 0; nt < 8; ++nt) MMA16816(acc[mt][nt], ahi, blo[nt]);
            }
        }
        __syncthreads();
    }

    const int rg = lane >> 2, tg = lane & 3;
    float* Cw = (btile == 0) ? C0 : C1;
#pragma unroll
    for (int mt = 0; mt < 4; ++mt)
#pragma unroll
        for (int nt = 0; nt < 8; ++nt) {
            int r = wm * 64 + mt * 16 + rg;
            int c = bcol0 + nt * 8 + tg * 2;
            *(float2*)&Cw[(size_t)r * ldc + c]       = make_float2(acc[mt][nt][0], acc[mt][nt][1]);
            *(float2*)&Cw[(size_t)(r + 8) * ldc + c] = make_float2(acc[mt][nt][2], acc[mt][nt][3]);
        }
}

// ---------------------------------------------------------------------------
// QKV projection: grid (32, 16) — each CTA does a pair of head tiles
// ---------------------------------------------------------------------------
__global__ __launch_bounds__(256, 1) void qkv_kernel(const float* __restrict__ x)
{
    const int m0 = blockIdx.x * 128;
    const int p  = blockIdx.y;           // pair 0..15
    const int t0 = 2 * p;

    const __nv_bfloat16* w3h = (const __nv_bfloat16*)g_enc;
    const __nv_bfloat16* w3l = w3h + W3_ELEMS;
    const __nv_bfloat16* B0h = w3h + (size_t)t0 * 2048 * 128;
    const __nv_bfloat16* B0l = w3l + (size_t)t0 * 2048 * 128;
    const __nv_bfloat16* B1h = B0h + 2048 * 128;
    const __nv_bfloat16* B1l = B0l + 2048 * 128;

    float* C0; int ldc;
    if (p < 8) {                         // Q heads 2p, 2p+1
        C0 = g_q + (size_t)m0 * (CN*CH) + t0 * CH; ldc = CN * CH;
    } else if (p < 12) {                 // K heads
        C0 = g_k + (size_t)m0 * (CK*CH) + (t0 - 16) * CH; ldc = CK * CH;
    } else {                             // V heads
        C0 = g_v + (size_t)m0 * (CK*CH) + (t0 - 24) * CH; ldc = CK * CH;
    }
    gemm2(x + (size_t)m0 * CD, CD, B0h, B0l, B1h, B1l, 128,
          C0, C0 + CH, ldc, CD);
}

// ---------------------------------------------------------------------------
// Output projection: grid (32, 8)
// ---------------------------------------------------------------------------
__global__ __launch_bounds__(256, 1) void oproj_kernel(float* __restrict__ out)
{
    const int m0 = blockIdx.x * 128;
    const int n0 = blockIdx.y * 256;
    const __nv_bfloat16* wo3h = (const __nv_bfloat16*)g_q;
    const __nv_bfloat16* wo3l = wo3h + WO3_ELEMS;
    gemm2(g_enc + (size_t)m0 * CD, CD,
          wo3h + n0, wo3l + n0, wo3h + n0 + 128, wo3l + n0 + 128, CD,
          out + (size_t)m0 * CD + n0, out + (size_t)m0 * CD + n0 + 128, CD, CD);
}

// ---------------------------------------------------------------------------
__global__ __launch_bounds__(256) void rope_kernel(const int* __restrict__ seg)
{
    int idx = blockIdx.x * blockDim.x + threadIdx.x;
    if (idx >= ROPE_QC + ROPE_KC) return;

    float* buf; int heads; float scal; int lidx;
    if (idx < ROPE_QC) {
        buf = g_q; heads = CN; scal = 0.08838834764831845f; lidx = idx;
    } else {
        buf = g_k; heads = CK; scal = 1.0f; lidx = idx - ROPE_QC;
    }
    const int i    = lidx & 63;
    const int rest = lidx >> 6;
    const int bt   = rest / heads;
    const int pos  = seg[bt];

    float ts = g_ts[i];
    float ang = (float)pos / ts;
    float s, c;
    sincosf(ang, &s, &c);

    float* p = buf + (size_t)rest * CH;
    float x1 = p[i];
    float x2 = p[i + 64];
    p[i]      = (x1 * c - x2 * s) * scal;
    p[i + 64] = (x2 * c + x1 * s) * scal;
}

// ---------------------------------------------------------------------------
__device__ __forceinline__ float softcap(float v)
{
    float x = v * (1.0f / 50.0f);
    float ax = fabsf(x);
    if (ax < 0.25f) {
        float x2 = x * x;
        float t = x * (1.0f + x2 * (-1.0f/3.0f + x2 * (2.0f/15.0f + x2 * (-17.0f/315.0f))));
        return t * 50.0f;
    }
    return tanhf(x) * 50.0f;
}

// ---------------------------------------------------------------------------
// Tensor-core flash attention (R16 version, measured 429us)
// ---------------------------------------------------------------------------
#define AROW 272
#define QTILE (128*AROW)
#define KTILE (64*AROW)
#define ASTG  (4*KTILE)
#define AKV0  (2*QTILE)
#define ATT_SMEM (AKV0 + 2*ASTG)

__global__ __launch_bounds__(256, 1) void attn_kernel()
{
    extern __shared__ char sma[];
    const uint32_t sb = (uint32_t)__cvta_generic_to_shared(sma);

    const int tid = threadIdx.x, lane = tid & 31, w = tid >> 5;
    const int rg = lane >> 2, tg = lane & 3;
    const int qt = blockIdx.x, n = blockIdx.y, b = blockIdx.z;
    const int kk = n >> 1;
    const int q0 = qt * 128;
    const int row0 = w * 16;

#pragma unroll
    for (int p = 0; p < 16; ++p) {
        int idx = tid + p * 256;
        int r = idx >> 5, c4 = idx & 31;
        float4 f = *(const float4*)(g_q +
            ((size_t)(b*CT + q0 + r) * CN + n) * CH + c4 * 4);
        float h0 = __bfloat162float(__float2bfloat16(f.x));
        float h1 = __bfloat162float(__float2bfloat16(f.y));
        float h2 = __bfloat162float(__float2bfloat16(f.z));
        float h3 = __bfloat162float(__float2bfloat16(f.w));
        uint32_t off = (uint32_t)(r * AROW + c4 * 8);
        *(uint2*)(sma + off)         = make_uint2(pack_bf2(h0, h1), pack_bf2(h2, h3));
        *(uint2*)(sma + QTILE + off) = make_uint2(pack_bf2(f.x - h0, f.y - h1),
                                                  pack_bf2(f.z - h2, f.w - h3));
    }

    int st0 = q0 - (CWIN - 1); if (st0 < 0) st0 = 0; st0 >>= 6;
    const int stL = (q0 + 127) >> 6;

    float4 kreg[8], vreg[8];
    const int sr = tid >> 5, sc = tid & 31;

    auto ldKV = [&](int st) {
        const int s0 = st * 64;
#pragma unroll
        for (int p = 0; p < 8; ++p) {
            int r = sr + p * 8;
            size_t off = ((size_t)(b*CT + s0 + r) * CK + kk) * CH + sc * 4;
            kreg[p] = *(const float4*)(g_k + off);
            vreg[p] = *(const float4*)(g_v + off);
        }
    };
    auto stKV = [&](int bsel) {
        const uint32_t kb = AKV0 + bsel * ASTG;
#pragma unroll
        for (int p = 0; p < 8; ++p) {
            int r = sr + p * 8;
            uint32_t off = (uint32_t)(r * AROW + sc * 8);
            float4 f = kreg[p];
            float h0 = __bfloat162float(__float2bfloat16(f.x));
            float h1 = __bfloat162float(__float2bfloat16(f.y));
            float h2 = __bfloat162float(__float2bfloat16(f.z));
            float h3 = __bfloat162float(__float2bfloat16(f.w));
            *(uint2*)(sma + kb + off) = make_uint2(pack_bf2(h0, h1), pack_bf2(h2, h3));
            *(uint2*)(sma + kb + KTILE + off) =
                make_uint2(pack_bf2(f.x - h0, f.y - h1), pack_bf2(f.z - h2, f.w - h3));
            f = vreg[p];
            h0 = __bfloat162float(__float2bfloat16(f.x));
            h1 = __bfloat162float(__float2bfloat16(f.y));
            h2 = __bfloat162float(__float2bfloat16(f.z));
            h3 = __bfloat162float(__float2bfloat16(f.w));
            *(uint2*)(sma + kb + 2*KTILE + off) = make_uint2(pack_bf2(h0, h1), pack_bf2(h2, h3));
            *(uint2*)(sma + kb + 3*KTILE + off) =
                make_uint2(pack_bf2(f.x - h0, f.y - h1), pack_bf2(f.z - h2, f.w - h3));
        }
    };

    ldKV(st0);
    stKV(0);
    if (st0 + 1 <= stL) ldKV(st0 + 1);
    __syncthreads();

    float m_i[2] = {-1e30f, -1e30f}, l_i[2] = {0.f, 0.f};
    float ao[16][4];
#pragma unroll
    for (int t = 0; t < 16; ++t)
#pragma unroll
        for (int c = 0; c < 4; ++c) ao[t][c] = 0.f;

    for (int st = st0; st <= stL; ++st) {
        const int bsel = (st - st0) & 1;
        const uint32_t kb  = sb + AKV0 + bsel * ASTG;
        const uint32_t vhB = kb + 2*KTILE;
        const int s0 = st * 64;

        if (st < stL) stKV(bsel ^ 1);
        if (st + 2 <= stL) ldKV(st + 2);

        float as[8][4];
#pragma unroll
        for (int nt = 0; nt < 8; ++nt)
#pragma unroll
            for (int c = 0; c < 4; ++c) as[nt][c] = 0.f;

#pragma unroll
        for (int kc = 0; kc < 8; ++kc) {
            uint32_t qa = sb + (row0 + (lane & 15)) * AROW + kc*32 + (lane >> 4) * 16;
            uint32_t qh[4], ql[4];
            LDSM4(qh, qa);
            LDSM4(ql, qa + QTILE);
#pragma unroll
            for (int np = 0; np < 2; ++np) {
                uint32_t kh4[2][4], kl4[2][4];
#pragma unroll
                for (int t = 0; t < 2; ++t) {
                    const int ntp = np*2 + t;
                    uint32_t ka = kb + (ntp*16 + (lane >> 4)*8 + (lane & 7)) * AROW
                                + kc*32 + ((lane >> 3) & 1) * 16;
                    LDSM4(kh4[t], ka);
                    LDSM4(kl4[t], ka + KTILE);
                }
#pragma unroll
                for (int t = 0; t < 2; ++t)
#pragma unroll
                    for (int j = 0; j < 2; ++j)
                        MMA16816(as[np*4 + t*2 + j], qh, &kh4[t][2*j]);
#pragma unroll
                for (int t = 0; t < 2; ++t)
#pragma unroll
                    for (int j = 0; j < 2; ++j)
                        MMA16816(as[np*4 + t*2 + j], ql, &kh4[t][2*j]);
#pragma unroll
                for (int t = 0; t < 2; ++t)
#pragma unroll
                    for (int j = 0; j < 2; ++j)
                        MMA16816(as[np*4 + t*2 + j], qh, &kl4[t][2*j]);
            }
        }

        float scale_[2];
#pragma unroll
        for (int hf = 0; hf < 2; ++hf) {
            const int qrow = q0 + row0 + rg + hf*8;
            float rm = -1e30f;
#pragma unroll
            for (int nt = 0; nt < 8; ++nt)
#pragma unroll
                for (int cc = 0; cc < 2; ++cc) {
                    const int scol = s0 + nt*8 + tg*2 + cc;
                    float xx = softcap(as[nt][hf*2 + cc]);
                    const bool valid = (scol <= qrow) && (qrow - scol < CWIN);
                    xx = valid ? xx : -1e30f;
                    as[nt][hf*2 + cc] = xx;
                    rm = fmaxf(rm, xx);
                }
            rm = fmaxf(rm, __shfl_xor_sync(0xffffffffu, rm, 1));
            rm = fmaxf(rm, __shfl_xor_sync(0xffffffffu, rm, 2));

            const float mn = fmaxf(m_i[hf], rm);
            scale_[hf] = __expf(m_i[hf] - mn);
            m_i[hf] = mn;

            float sl = 0.f;
#pragma unroll
            for (int nt = 0; nt < 8; ++nt)
#pragma unroll
                for (int cc = 0; cc < 2; ++cc) {
                    float v = as[nt][hf*2 + cc];
                    float p = (v > -1e29f) ? __expf(v - mn) : 0.f;
                    as[nt][hf*2 + cc] = p;
                    sl += p;
                }
            sl += __shfl_xor_sync(0xffffffffu, sl, 1);
            sl += __shfl_xor_sync(0xffffffffu, sl, 2);
            l_i[hf] = l_i[hf] * scale_[hf] + sl;
        }
#pragma unroll
        for (int nt = 0; nt < 16; ++nt) {
            ao[nt][0] *= scale_[0]; ao[nt][1] *= scale_[0];
            ao[nt][2] *= scale_[1]; ao[nt][3] *= scale_[1];
        }

#pragma unroll
        for (int kc = 0; kc < 4; ++kc) {
            uint32_t ph[4], pl[4];
#pragma unroll
            for (int half = 0; half < 2; ++half) {
                const int nt = 2*kc + half;
                float p0 = as[nt][0], p1 = as[nt][1], p2 = as[nt][2], p3 = as[nt][3];
                float h0 = __bfloat162float(__float2bfloat16(p0));
                float h1 = __bfloat162float(__float2bfloat16(p1));
                float h2 = __bfloat162float(__float2bfloat16(p2));
                float h3 = __bfloat162float(__float2bfloat16(p3));
                ph[half*2 + 0] = pack_bf2(p0, p1);
                ph[half*2 + 1] = pack_bf2(p2, p3);
                pl[half*2 + 0] = pack_bf2(p0 - h0, p1 - h1);
                pl[half*2 + 1] = pack_bf2(p2 - h2, p3 - h3);
            }
#pragma unroll
            for (int np = 0; np < 4; ++np) {
                uint32_t vh4[2][4], vl4[2][4];
#pragma unroll
                for (int t = 0; t < 2; ++t) {
                    const int ntp = np*2 + t;
                    uint32_t va = vhB + (kc*16 + (lane & 15)) * AROW
                                + ntp*32 + (lane >> 4) * 16;
                    LDSM4T(vh4[t], va);
                    LDSM4T(vl4[t], va + KTILE);
                }
#pragma unroll
                for (int t = 0; t < 2; ++t)
#pragma unroll
                    for (int j = 0; j < 2; ++j)
                        MMA16816(ao[np*4 + t*2 + j], ph, &vh4[t][2*j]);
#pragma unroll
                for (int t = 0; t < 2; ++t)
#pragma unroll
                    for (int j = 0; j < 2; ++j)
                        MMA16816(ao[np*4 + t*2 + j], pl, &vh4[t][2*j]);
#pragma unroll
                for (int t = 0; t < 2; ++t)
#pragma unroll
                    for (int j = 0; j < 2; ++j)
                        MMA16816(ao[np*4 + t*2 + j], ph, &vl4[t][2*j]);
            }
        }

        __syncthreads();
    }

#pragma unroll
    for (int hf = 0; hf < 2; ++hf) {
        const int qrow = q0 + row0 + rg + hf*8;
        const float inv = 1.0f / l_i[hf];
        float* o = g_enc + ((size_t)(b*CT + qrow) * CN + n) * CH;
#pragma unroll
        for (int nt = 0; nt < 16; ++nt)
            *(float2*)(o + nt*8 + tg*2) =
                make_float2(ao[nt][hf*2 + 0] * inv, ao[nt][hf*2 + 1] * inv);
    }
}

// ---------------------------------------------------------------------------
extern "C" void kernel_launch(void* const* d_in, const int* in_sizes, int n_in,
                              void* d_out, int out_size)
{
    const float* x   = (const float*)d_in[0];
    const float* wq  = (const float*)d_in[1];
    const float* wkv = (const float*)d_in[2];
    const float* wo  = (const float*)d_in[3];
    const int*   seg = (const int*)d_in[4];
    float* out = (float*)d_out;

    cudaFuncSetAttribute(attn_kernel,
                         cudaFuncAttributeMaxDynamicSharedMemorySize, ATT_SMEM);
    cudaFuncSetAttribute(qkv_kernel,
                         cudaFuncAttributeMaxDynamicSharedMemorySize, GEM2_SMEM);
    cudaFuncSetAttribute(oproj_kernel,
                         cudaFuncAttributeMaxDynamicSharedMemorySize, GEM2_SMEM);

    rope_init_kernel<<<1, 64>>>();

    // one-time weight split (into g_enc)
    split_w_kernel<<<(W3_ELEMS + 255)/256, 256>>>(wq, wkv);

    // QKV on tensor cores (B pre-split, 128x256 tiles)
    qkv_kernel<<<dim3(32, 16), 256, GEM2_SMEM>>>(x);

    rope_kernel<<<(ROPE_QC + ROPE_KC + 255)/256, 256>>>(seg);

    // attention -> writes encoded into g_enc (weights no longer needed)
    attn_kernel<<<dim3(CT/128, CN, CB), 256, ATT_SMEM>>>();

    // split wo into g_q (dead after attention), then O projection
    split_wo_kernel<<<(WO3_ELEMS + 255)/256, 256>>>(wo);
    oproj_kernel<<<dim3(32, 8), 256, GEM2_SMEM>>>(out);
}